// round 15
// baseline (speedup 1.0000x reference)
#include <cuda_runtime.h>
#include <float.h>

#define E_DIM 512
#define H_NUM 8
#define D_DIM 64
#define S_LEN 2048
#define B_NUM 4
#define M_ROWS (B_NUM * S_LEN)   // 8192
#define NQB (S_LEN / 128)        // 16 q-tiles per (b,h)

// Scratch (no allocations allowed). Device globals are zero-initialized at
// module load; compacted-tile tail rows [nv, pad128) are never written and nv
// is constant per run, so they stay zero (no pad kernel needed).
__device__ float g_vfull[(size_t)M_ROWS * E_DIM];     // v projection (all rows)
__device__ float g_attn[(size_t)M_ROWS * E_DIM];      // attention output
__device__ float g_qc[(size_t)M_ROWS * E_DIM];        // compacted q (roped, scaled, tf32)
__device__ float g_kc[(size_t)M_ROWS * E_DIM];        // compacted k (roped, tf32)
__device__ float g_vc[(size_t)M_ROWS * E_DIM];        // compacted v (tf32)
__device__ int   g_qidx[M_ROWS];                      // compact pos -> orig s
__device__ int   g_pos[M_ROWS];                       // orig s -> compact pos | -1
__device__ int   g_nv[B_NUM];                         // valid count per batch
__device__ float g_rt[S_LEN * 32];                    // rope table: (cos,sin) x16
__device__ float g_opart[(size_t)2 * B_NUM * H_NUM * S_LEN * D_DIM];  // 67 MB
__device__ float g_lpart[(size_t)2 * B_NUM * H_NUM * S_LEN];          // 0.5 MB

// ---------------- tf32 / async helpers ----------------
__device__ __forceinline__ float to_tf32(float x) {
    float y; asm("cvt.rna.tf32.f32 %0, %1;" : "=f"(y) : "f"(x)); return y;
}
__device__ __forceinline__ void mma16n8k8(float c[4], const unsigned a[4],
                                          unsigned b0, unsigned b1) {
    asm volatile(
        "mma.sync.aligned.m16n8k8.row.col.f32.tf32.tf32.f32 "
        "{%0,%1,%2,%3}, {%4,%5,%6,%7}, {%8,%9}, {%0,%1,%2,%3};"
        : "+f"(c[0]), "+f"(c[1]), "+f"(c[2]), "+f"(c[3])
        : "r"(a[0]), "r"(a[1]), "r"(a[2]), "r"(a[3]), "r"(b0), "r"(b1));
}
__device__ __forceinline__ unsigned smem_u32(const void* p) {
    return (unsigned)__cvta_generic_to_shared(p);
}
__device__ __forceinline__ void cp_async16(unsigned s, const void* g) {
    asm volatile("cp.async.cg.shared.global [%0], [%1], 16;" :: "r"(s), "l"(g));
}
__device__ __forceinline__ void cp_commit() {
    asm volatile("cp.async.commit_group;" ::: "memory");
}
template<int N>
__device__ __forceinline__ void cp_wait() {
    asm volatile("cp.async.wait_group %0;" :: "n"(N) : "memory");
}

// Q pre-scale folds log2(e): softmax numerators via exp2f.
#define Q_SCALE 0.18033688f   // 0.125 * 1.4426950408889634

// ---------------------------------------------------------------------------
// Shared GEMM compute core: 4x2 warp tiling (warp = 32 rows x 64 cols).
// B-fragments shared across the warp's 2 M-tiles: LDS per chunk per warp
// drops 144 -> 96. A-frags staged per kt-half (16 regs, unchanged pressure).
// Accumulation order per output (kt ascending) is identical to the 8x1 code.
// ---------------------------------------------------------------------------
#define GEMM_CHUNK_COMPUTE(As, Bs, Cacc, wm, wn, g, tig)                      \
    do {                                                                      \
        _Pragma("unroll")                                                     \
        for (int hh = 0; hh < 2; hh++) {                                      \
            unsigned afr[2][2][4];                                            \
            _Pragma("unroll")                                                 \
            for (int mt = 0; mt < 2; mt++)                                    \
                _Pragma("unroll")                                             \
                for (int jj = 0; jj < 2; jj++) {                              \
                    int ar = (wm) * 32 + mt * 16;                             \
                    int kc = (2 * hh + jj) * 8 + (tig);                       \
                    afr[mt][jj][0] = __float_as_uint(As[ar + (g)][kc]);       \
                    afr[mt][jj][1] = __float_as_uint(As[ar + (g) + 8][kc]);   \
                    afr[mt][jj][2] = __float_as_uint(As[ar + (g)][kc + 4]);   \
                    afr[mt][jj][3] = __float_as_uint(As[ar + (g) + 8][kc + 4]);\
                }                                                             \
            _Pragma("unroll")                                                 \
            for (int nt = 0; nt < 8; nt++) {                                  \
                int br = (wn) * 64 + nt * 8 + (g);                            \
                _Pragma("unroll")                                             \
                for (int jj = 0; jj < 2; jj++) {                              \
                    int kc = (2 * hh + jj) * 8 + (tig);                       \
                    unsigned b0 = __float_as_uint(Bs[br][kc]);                \
                    unsigned b1 = __float_as_uint(Bs[br][kc + 4]);            \
                    mma16n8k8(Cacc[0][nt], afr[0][jj], b0, b1);               \
                    mma16n8k8(Cacc[1][nt], afr[1][jj], b0, b1);               \
                }                                                             \
            }                                                                 \
        }                                                                     \
    } while (0)

// ---------------------------------------------------------------------------
// Fused QKV projection (grid (12, 64)):
//   blockIdx.x 0..3  -> V columns on DENSE rows (Vfull + scatter Vc).
//   blockIdx.x 4..11 -> Q/K columns on GATHERED valid rows; early-exit;
//       fused RoPE+scale+tf32 epilogue into Qc/Kc.
// ---------------------------------------------------------------------------
__global__ __launch_bounds__(256)
void gemm_qkv(const float* __restrict__ x, const float* __restrict__ W_in,
              const int* __restrict__ qidx, const int* __restrict__ pos,
              const int* __restrict__ nv, const float* __restrict__ rt,
              float* __restrict__ Vfull, float* __restrict__ Qc,
              float* __restrict__ Kc, float* __restrict__ Vc) {
    const int BK = 32, K = 512;
    const int row0 = blockIdx.y * 128;
    const int bb = row0 >> 11;
    const int nvb = nv[bb];
    const bool isV = (blockIdx.x < 4);
    const int colblk = isV ? blockIdx.x : (blockIdx.x - 4);
    if (!isV && (row0 & 2047) >= ((nvb + 127) & ~127)) return;

    __shared__ float As[128][BK + 4];
    __shared__ float Bs[128][BK + 4];
    __shared__ int rowidx[128];

    const int tid = threadIdx.x;
    const int w = tid >> 5, lane = tid & 31;
    const int g = lane >> 2, tig = lane & 3;
    const int wm = w & 3, wn = w >> 2;       // 4x2 warp tiling

    for (int r = tid; r < 128; r += 256) {
        int idx;
        if (isV) {
            idx = row0 + r;
        } else {
            int p = (row0 & 2047) + r;
            int pc = (p < nvb) ? p : (nvb - 1);
            idx = (bb << 11) + qidx[(bb << 11) + pc];
        }
        rowidx[r] = idx;
    }
    __syncthreads();

    int rr[4];
    #pragma unroll
    for (int j = 0; j < 4; j++) rr[j] = rowidx[(tid + j * 256) >> 3];

    const float* Bp = W_in + (size_t)(isV ? (1024 + colblk * 128)
                                          : (colblk * 128)) * K;

    float Cacc[2][8][4];
    #pragma unroll
    for (int mt = 0; mt < 2; mt++)
        #pragma unroll
        for (int nt = 0; nt < 8; nt++)
            #pragma unroll
            for (int j = 0; j < 4; j++) Cacc[mt][nt][j] = 0.f;

    float4 pA[4], pB[4];
    #pragma unroll
    for (int j = 0; j < 4; j++) {
        int i = tid + j * 256, r = i >> 3, c4 = (i & 7) * 4;
        pA[j] = *(const float4*)&x[(size_t)rr[j] * K + c4];
        pB[j] = *(const float4*)&Bp[(size_t)r * K + c4];
    }
    #pragma unroll
    for (int j = 0; j < 4; j++) {
        int i = tid + j * 256, r = i >> 3, c4 = (i & 7) * 4;
        float4 ta, tb;
        ta.x = to_tf32(pA[j].x); ta.y = to_tf32(pA[j].y);
        ta.z = to_tf32(pA[j].z); ta.w = to_tf32(pA[j].w);
        tb.x = to_tf32(pB[j].x); tb.y = to_tf32(pB[j].y);
        tb.z = to_tf32(pB[j].z); tb.w = to_tf32(pB[j].w);
        *(float4*)&As[r][c4] = ta;
        *(float4*)&Bs[r][c4] = tb;
    }
    __syncthreads();

    const int NC = K / BK;     // 16
    for (int ch = 0; ch < NC; ch++) {
        const bool more = (ch + 1) < NC;
        if (more) {
            const int kn = (ch + 1) * BK;
            #pragma unroll
            for (int j = 0; j < 4; j++) {
                int i = tid + j * 256, r = i >> 3, c4 = (i & 7) * 4;
                pA[j] = *(const float4*)&x[(size_t)rr[j] * K + kn + c4];
                pB[j] = *(const float4*)&Bp[(size_t)r * K + kn + c4];
            }
        }
        GEMM_CHUNK_COMPUTE(As, Bs, Cacc, wm, wn, g, tig);
        if (more) {
            __syncthreads();
            #pragma unroll
            for (int j = 0; j < 4; j++) {
                int i = tid + j * 256, r = i >> 3, c4 = (i & 7) * 4;
                float4 ta, tb;
                ta.x = to_tf32(pA[j].x); ta.y = to_tf32(pA[j].y);
                ta.z = to_tf32(pA[j].z); ta.w = to_tf32(pA[j].w);
                tb.x = to_tf32(pB[j].x); tb.y = to_tf32(pB[j].y);
                tb.z = to_tf32(pB[j].z); tb.w = to_tf32(pB[j].w);
                *(float4*)&As[r][c4] = ta;
                *(float4*)&Bs[r][c4] = tb;
            }
            __syncthreads();
        }
    }

    if (isV) {
        #pragma unroll
        for (int mt = 0; mt < 2; mt++) {
            const int s1 = row0 + wm * 32 + mt * 16 + g, s2 = s1 + 8;
            const int ps1 = pos[s1], ps2 = pos[s2];
            #pragma unroll
            for (int nt = 0; nt < 8; nt++) {
                const int col = colblk * 128 + wn * 64 + nt * 8 + 2 * tig;
                {
                    float2 o; o.x = Cacc[mt][nt][0]; o.y = Cacc[mt][nt][1];
                    *(float2*)&Vfull[(size_t)s1 * E_DIM + col] = o;
                    if (ps1 >= 0) {
                        float2 t; t.x = to_tf32(o.x); t.y = to_tf32(o.y);
                        *(float2*)&Vc[(size_t)((bb << 11) + ps1) * E_DIM + col] = t;
                    }
                }
                {
                    float2 o; o.x = Cacc[mt][nt][2]; o.y = Cacc[mt][nt][3];
                    *(float2*)&Vfull[(size_t)s2 * E_DIM + col] = o;
                    if (ps2 >= 0) {
                        float2 t; t.x = to_tf32(o.x); t.y = to_tf32(o.y);
                        *(float2*)&Vc[(size_t)((bb << 11) + ps2) * E_DIM + col] = t;
                    }
                }
            }
        }
    } else {
        const int base = bb << 11;
        const int col0 = colblk * 128;
        const bool isQ = (col0 < 512);
        float* dst = isQ ? Qc : Kc;
        const float scale = isQ ? Q_SCALE : 1.0f;
        #pragma unroll
        for (int mt = 0; mt < 2; mt++) {
            const int pl1 = (row0 & 2047) + wm * 32 + mt * 16 + g;
            const int pl2 = pl1 + 8;
            const bool ok1 = pl1 < nvb, ok2 = pl2 < nvb;
            const int s1 = ok1 ? qidx[base + pl1] : 0;
            const int s2 = ok2 ? qidx[base + pl2] : 0;
            #pragma unroll
            for (int nt = 0; nt < 8; nt++) {
                const int col = col0 + wn * 64 + nt * 8 + 2 * tig;
                const int d = col & 63;
                const int cq = col & 511;
                if (ok1) {
                    float c0 = Cacc[mt][nt][0], c1 = Cacc[mt][nt][1];
                    if (d < 32) {
                        float2 t = *(const float2*)(rt + s1 * 32 + d);
                        float r0 = c0 * t.x - c1 * t.y;
                        float r1 = c0 * t.y + c1 * t.x;
                        c0 = r0; c1 = r1;
                    }
                    float2 o; o.x = to_tf32(c0 * scale); o.y = to_tf32(c1 * scale);
                    *(float2*)&dst[(size_t)(base + pl1) * E_DIM + cq] = o;
                }
                if (ok2) {
                    float c0 = Cacc[mt][nt][2], c1 = Cacc[mt][nt][3];
                    if (d < 32) {
                        float2 t = *(const float2*)(rt + s2 * 32 + d);
                        float r0 = c0 * t.x - c1 * t.y;
                        float r1 = c0 * t.y + c1 * t.x;
                        c0 = r0; c1 = r1;
                    }
                    float2 o; o.x = to_tf32(c0 * scale); o.y = to_tf32(c1 * scale);
                    *(float2*)&dst[(size_t)(base + pl2) * E_DIM + cq] = o;
                }
            }
        }
    }
}

// ---------------------------------------------------------------------------
// tf32 GEMM C = A @ B^T — output projection (4x2 warp tiling).
// ---------------------------------------------------------------------------
template<int BM, int BN, int BK>
__global__ __launch_bounds__(256)
void gemm_tf32(const float* __restrict__ A, const float* __restrict__ B,
               float* __restrict__ C, int M, int N, int K) {
    __shared__ float As[BM][BK + 4];
    __shared__ float Bs[BN][BK + 4];
    const int tid = threadIdx.x;
    const int w = tid >> 5, lane = tid & 31;
    const int g = lane >> 2, tig = lane & 3;
    const int wm = w & 3, wn = w >> 2;
    const int row0 = blockIdx.y * BM, col0 = blockIdx.x * BN;

    float Cacc[2][8][4];
    #pragma unroll
    for (int mt = 0; mt < 2; mt++)
        #pragma unroll
        for (int nt = 0; nt < 8; nt++)
            #pragma unroll
            for (int j = 0; j < 4; j++) Cacc[mt][nt][j] = 0.f;

    float4 pA[4], pB[4];
    #pragma unroll
    for (int j = 0; j < 4; j++) {
        int i = tid + j * 256, r = i >> 3, c4 = (i & 7) * 4;
        pA[j] = *(const float4*)&A[(size_t)(row0 + r) * K + c4];
        pB[j] = *(const float4*)&B[(size_t)(col0 + r) * K + c4];
    }
    #pragma unroll
    for (int j = 0; j < 4; j++) {
        int i = tid + j * 256, r = i >> 3, c4 = (i & 7) * 4;
        float4 ta, tb;
        ta.x = to_tf32(pA[j].x); ta.y = to_tf32(pA[j].y);
        ta.z = to_tf32(pA[j].z); ta.w = to_tf32(pA[j].w);
        tb.x = to_tf32(pB[j].x); tb.y = to_tf32(pB[j].y);
        tb.z = to_tf32(pB[j].z); tb.w = to_tf32(pB[j].w);
        *(float4*)&As[r][c4] = ta;
        *(float4*)&Bs[r][c4] = tb;
    }
    __syncthreads();

    const int NC = K / BK;
    for (int ch = 0; ch < NC; ch++) {
        const bool more = (ch + 1) < NC;
        if (more) {
            const int kn = (ch + 1) * BK;
            #pragma unroll
            for (int j = 0; j < 4; j++) {
                int i = tid + j * 256, r = i >> 3, c4 = (i & 7) * 4;
                pA[j] = *(const float4*)&A[(size_t)(row0 + r) * K + kn + c4];
                pB[j] = *(const float4*)&B[(size_t)(col0 + r) * K + kn + c4];
            }
        }
        GEMM_CHUNK_COMPUTE(As, Bs, Cacc, wm, wn, g, tig);
        if (more) {
            __syncthreads();
            #pragma unroll
            for (int j = 0; j < 4; j++) {
                int i = tid + j * 256, r = i >> 3, c4 = (i & 7) * 4;
                float4 ta, tb;
                ta.x = to_tf32(pA[j].x); ta.y = to_tf32(pA[j].y);
                ta.z = to_tf32(pA[j].z); ta.w = to_tf32(pA[j].w);
                tb.x = to_tf32(pB[j].x); tb.y = to_tf32(pB[j].y);
                tb.z = to_tf32(pB[j].z); tb.w = to_tf32(pB[j].w);
                *(float4*)&As[r][c4] = ta;
                *(float4*)&Bs[r][c4] = tb;
            }
            __syncthreads();
        }
    }

    #pragma unroll
    for (int mt = 0; mt < 2; mt++) {
        int r1 = row0 + wm * 32 + mt * 16 + g;
        #pragma unroll
        for (int nt = 0; nt < 8; nt++) {
            int col = col0 + wn * 64 + nt * 8 + 2 * tig;
            float2 o1; o1.x = Cacc[mt][nt][0]; o1.y = Cacc[mt][nt][1];
            float2 o2; o2.x = Cacc[mt][nt][2]; o2.y = Cacc[mt][nt][3];
            *(float2*)&C[(size_t)r1 * N + col] = o1;
            *(float2*)&C[(size_t)(r1 + 8) * N + col] = o2;
        }
    }
}

// ---------------------------------------------------------------------------
// Per-batch mask prefix scan; emits qidx, pos, nv.
// ---------------------------------------------------------------------------
__global__ void mask_compact(const int* __restrict__ mask,
                             int* __restrict__ qidx, int* __restrict__ pos,
                             int* __restrict__ nv) {
    __shared__ int ps[1024];
    const int b = blockIdx.x, t = threadIdx.x;
    const int m0 = mask[b * S_LEN + 2 * t] != 0;
    const int m1 = mask[b * S_LEN + 2 * t + 1] != 0;
    ps[t] = m0 + m1;
    __syncthreads();
    #pragma unroll
    for (int off = 1; off < 1024; off <<= 1) {
        int v = ps[t];
        int a = (t >= off) ? ps[t - off] : 0;
        __syncthreads();
        ps[t] = v + a;
        __syncthreads();
    }
    int excl = t ? ps[t - 1] : 0;
    int c0 = excl + m0;
    int c1 = c0 + m1;
    if (m0) qidx[b * S_LEN + c0 - 1] = 2 * t;
    if (m1) qidx[b * S_LEN + c1 - 1] = 2 * t + 1;
    pos[b * S_LEN + 2 * t]     = m0 ? (c0 - 1) : -1;
    pos[b * S_LEN + 2 * t + 1] = m1 ? (c1 - 1) : -1;
    if (t == 1023) nv[b] = c1;
}

// ---------------------------------------------------------------------------
// RoPE table.
// ---------------------------------------------------------------------------
__global__ void rope_table(float* __restrict__ rt) {
    int idx = blockIdx.x * blockDim.x + threadIdx.x;    // < 2048*16
    int pair = idx & 15, s = idx >> 4;
    float freq = powf(10000.f, -(float)(2 * pair) / 32.f);
    float sn, cs;
    sincosf((float)s * freq, &sn, &cs);
    rt[s * 32 + 2 * pair]     = cs;
    rt[s * 32 + 2 * pair + 1] = sn;
}

// ---------------------------------------------------------------------------
// Split-K tensor-core flash attention — SINGLE barrier per k-tile iteration:
//   cp_wait<0>; __syncthreads; prefetch(it+1); compute(it)
// The barrier both publishes tile it and proves all warps finished
// compute(it-1), so the prefetch into buf (it+1)&1 (== buf (it-1)&1) is safe.
// ---------------------------------------------------------------------------
__global__ __launch_bounds__(256)
void flash_attn_c4(const float* __restrict__ Qc, const float* __restrict__ Kc,
                   const float* __restrict__ Vc, const int* __restrict__ nv,
                   float* __restrict__ opart, float* __restrict__ lpart) {
    extern __shared__ float sm[];
    float (*Ps)[68] = (float(*)[68])(sm + 17408);

    const int b = blockIdx.z, h = blockIdx.y;
    const int raw = gridDim.x - 1 - blockIdx.x;     // heavy blocks first
    const int qb = raw >> 1, half = raw & 1;
    const int n = nv[b];
    if (qb * 128 >= n) return;

    const int itStart = half ? (qb + 1) : 0;
    const int itEnd   = half ? (2 * qb + 2) : (qb + 1);   // exclusive

    const int tid = threadIdx.x;
    const int w = tid >> 5, lane = tid & 31;
    const int g = lane >> 2, tig = lane & 3;
    const int p1 = qb * 128 + w * 16 + g, p2 = p1 + 8;

    const float* qsec = Qc + (size_t)(b * S_LEN) * E_DIM + h * D_DIM;
    const float* ksec = Kc + (size_t)(b * S_LEN) * E_DIM + h * D_DIM;
    const float* vsec = Vc + (size_t)(b * S_LEN) * E_DIM + h * D_DIM;

    // prologue: async-fill first tile
    {
        float* Kb = sm + (itStart & 1) * 8704;
        float* Vb = Kb + 64 * 68;
        const int t00 = itStart * 64;
        #pragma unroll
        for (int j = 0; j < 4; j++) {
            int i = tid + j * 256;
            int r = i >> 4, c4 = (i & 15) * 4;
            cp_async16(smem_u32(&Kb[r * 68 + c4]), ksec + (size_t)(t00 + r) * E_DIM + c4);
            cp_async16(smem_u32(&Vb[r * 68 + c4]), vsec + (size_t)(t00 + r) * E_DIM + c4);
        }
        cp_commit();
    }

    for (int i = tid; i < 128 * 16; i += 256) {
        int r = i >> 4, c4 = (i & 15) * 4;
        *(float4*)&Ps[r][c4] =
            *(const float4*)(qsec + (size_t)(qb * 128 + r) * E_DIM + c4);
    }
    __syncthreads();
    unsigned qa[8][4];
    #pragma unroll
    for (int kt = 0; kt < 8; kt++) {
        qa[kt][0] = __float_as_uint(Ps[w * 16 + g][kt * 8 + tig]);
        qa[kt][1] = __float_as_uint(Ps[w * 16 + g + 8][kt * 8 + tig]);
        qa[kt][2] = __float_as_uint(Ps[w * 16 + g][kt * 8 + tig + 4]);
        qa[kt][3] = __float_as_uint(Ps[w * 16 + g + 8][kt * 8 + tig + 4]);
    }

    float O[8][4];
    #pragma unroll
    for (int nt = 0; nt < 8; nt++)
        #pragma unroll
        for (int j = 0; j < 4; j++) O[nt][j] = 0.f;
    float l1 = 0.f, l2 = 0.f;

    for (int it = itStart; it < itEnd; ++it) {
        cp_wait<0>();           // tile it landed (this thread's copies)
        __syncthreads();        // publish tile it; all warps past compute(it-1)
        if (it + 1 < itEnd) {   // prefetch next tile (overlaps compute below)
            float* Kb = sm + ((it + 1) & 1) * 8704;
            float* Vb = Kb + 64 * 68;
            const int t0n = (it + 1) * 64;
            #pragma unroll
            for (int j = 0; j < 4; j++) {
                int i = tid + j * 256;
                int r = i >> 4, c4 = (i & 15) * 4;
                cp_async16(smem_u32(&Kb[r * 68 + c4]),
                           ksec + (size_t)(t0n + r) * E_DIM + c4);
                cp_async16(smem_u32(&Vb[r * 68 + c4]),
                           vsec + (size_t)(t0n + r) * E_DIM + c4);
            }
            cp_commit();
        }

        const float* Kb = sm + (it & 1) * 8704;
        const float* Vb = Kb + 64 * 68;
        const int t0 = it * 64;

        float C[8][4];
        #pragma unroll
        for (int nt = 0; nt < 8; nt++)
            #pragma unroll
            for (int j = 0; j < 4; j++) C[nt][j] = 0.f;
        #pragma unroll
        for (int kt = 0; kt < 8; kt++) {
            #pragma unroll
            for (int nt = 0; nt < 8; nt++) {
                unsigned b0 = __float_as_uint(Kb[(nt * 8 + g) * 68 + kt * 8 + tig]);
                unsigned b1 = __float_as_uint(Kb[(nt * 8 + g) * 68 + kt * 8 + tig + 4]);
                mma16n8k8(C[nt], qa[kt], b0, b1);
            }
        }

        if (it >= 2 * qb) {
            #pragma unroll
            for (int nt = 0; nt < 8; nt++) {
                int tp = t0 + nt * 8 + 2 * tig;
                if (tp     > p1) C[nt][0] = -30000.f;
                if (tp + 1 > p1) C[nt][1] = -30000.f;
                if (tp     > p2) C[nt][2] = -30000.f;
                if (tp + 1 > p2) C[nt][3] = -30000.f;
            }
        }

        float sum1 = 0.f, sum2 = 0.f;
        #pragma unroll
        for (int nt = 0; nt < 8; nt++) {
            C[nt][0] = exp2f(C[nt][0]); sum1 += C[nt][0];
            C[nt][1] = exp2f(C[nt][1]); sum1 += C[nt][1];
            C[nt][2] = exp2f(C[nt][2]); sum2 += C[nt][2];
            C[nt][3] = exp2f(C[nt][3]); sum2 += C[nt][3];
        }
        sum1 += __shfl_xor_sync(0xffffffffu, sum1, 1);
        sum1 += __shfl_xor_sync(0xffffffffu, sum1, 2);
        sum2 += __shfl_xor_sync(0xffffffffu, sum2, 1);
        sum2 += __shfl_xor_sync(0xffffffffu, sum2, 2);
        l1 += sum1;
        l2 += sum2;

        #pragma unroll
        for (int nt = 0; nt < 8; nt++) {
            int r = w * 16 + g, c = nt * 8 + 2 * tig;
            Ps[r][c]         = to_tf32(C[nt][0]);
            Ps[r][c + 1]     = to_tf32(C[nt][1]);
            Ps[r + 8][c]     = to_tf32(C[nt][2]);
            Ps[r + 8][c + 1] = to_tf32(C[nt][3]);
        }
        __syncwarp();

        #pragma unroll
        for (int kt = 0; kt < 8; kt++) {
            unsigned pa[4];
            pa[0] = __float_as_uint(Ps[w * 16 + g][kt * 8 + tig]);
            pa[1] = __float_as_uint(Ps[w * 16 + g + 8][kt * 8 + tig]);
            pa[2] = __float_as_uint(Ps[w * 16 + g][kt * 8 + tig + 4]);
            pa[3] = __float_as_uint(Ps[w * 16 + g + 8][kt * 8 + tig + 4]);
            #pragma unroll
            for (int nt = 0; nt < 8; nt++) {
                unsigned b0 = __float_as_uint(Vb[(kt * 8 + tig) * 68 + nt * 8 + g]);
                unsigned b1 = __float_as_uint(Vb[(kt * 8 + tig + 4) * 68 + nt * 8 + g]);
                mma16n8k8(O[nt], pa, b0, b1);
            }
        }
        // no trailing barrier: next iteration's single barrier covers reuse
    }

    const size_t base = ((((size_t)half * B_NUM + b) * H_NUM + h) * S_LEN);
    const int ok1 = (p1 < n), ok2 = (p2 < n);
    float* op1 = opart + (base + p1) * D_DIM;
    float* op2 = opart + (base + p2) * D_DIM;
    #pragma unroll
    for (int nt = 0; nt < 8; nt++) {
        int c = nt * 8 + 2 * tig;
        if (ok1) { float2 o; o.x = O[nt][0]; o.y = O[nt][1]; *(float2*)(op1 + c) = o; }
        if (ok2) { float2 o; o.x = O[nt][2]; o.y = O[nt][3]; *(float2*)(op2 + c) = o; }
    }
    if (tig == 0) {
        if (ok1) lpart[base + p1] = l1;
        if (ok2) lpart[base + p2] = l2;
    }
}

// ---------------------------------------------------------------------------
// Fused merge + masked v-copy.
// ---------------------------------------------------------------------------
__global__ void merge_vcopy(const float* __restrict__ opart,
                            const float* __restrict__ lpart,
                            const int* __restrict__ pos,
                            const int* __restrict__ mask,
                            const float* __restrict__ Vfull,
                            float* __restrict__ out) {
    const int b = blockIdx.y, s = blockIdx.x, t = threadIdx.x;
    if (mask[b * S_LEN + s] == 0) {
        const float4* src = (const float4*)(Vfull + (size_t)(b * S_LEN + s) * E_DIM);
        ((float4*)(out + (size_t)(b * S_LEN + s) * E_DIM))[t] = src[t];
        return;
    }
    const int p = pos[b * S_LEN + s];
    const int h = t >> 4, c4 = (t & 15) * 4;
    const size_t r0 = ((((size_t)0 * B_NUM + b) * H_NUM + h) * S_LEN + p);
    const size_t r1 = ((((size_t)1 * B_NUM + b) * H_NUM + h) * S_LEN + p);
    const float inv = 1.f / (lpart[r0] + lpart[r1]);
    float4 o0 = *(const float4*)(opart + r0 * D_DIM + c4);
    float4 o1 = *(const float4*)(opart + r1 * D_DIM + c4);
    float4 o;
    o.x = (o0.x + o1.x) * inv; o.y = (o0.y + o1.y) * inv;
    o.z = (o0.z + o1.z) * inv; o.w = (o0.w + o1.w) * inv;
    *(float4*)(out + (size_t)(b * S_LEN + s) * E_DIM + h * D_DIM + c4) = o;
}

// ---------------------------------------------------------------------------
extern "C" void kernel_launch(void* const* d_in, const int* in_sizes, int n_in,
                              void* d_out, int out_size) {
    const float* x     = (const float*)d_in[0];
    const int*   mask  = (const int*)d_in[1];     // bool -> int32 in harness
    const float* W_in  = (const float*)d_in[2];
    const float* W_out = (const float*)d_in[3];
    float*       out   = (float*)d_out;

    float *Vfull, *attn, *Qc, *Kc, *Vc, *rt, *op, *lp; int *qidx, *pos, *nv;
    cudaGetSymbolAddress((void**)&Vfull, g_vfull);
    cudaGetSymbolAddress((void**)&attn,  g_attn);
    cudaGetSymbolAddress((void**)&Qc,    g_qc);
    cudaGetSymbolAddress((void**)&Kc,    g_kc);
    cudaGetSymbolAddress((void**)&Vc,    g_vc);
    cudaGetSymbolAddress((void**)&rt,    g_rt);
    cudaGetSymbolAddress((void**)&op,    g_opart);
    cudaGetSymbolAddress((void**)&lp,    g_lpart);
    cudaGetSymbolAddress((void**)&qidx,  g_qidx);
    cudaGetSymbolAddress((void**)&pos,   g_pos);
    cudaGetSymbolAddress((void**)&nv,    g_nv);

    const int ATT_SMEM = 26112 * sizeof(float);   // 104448 B
    cudaFuncSetAttribute(flash_attn_c4,
                         cudaFuncAttributeMaxDynamicSharedMemorySize, ATT_SMEM);

    // 1) mask scan + rope table
    mask_compact<<<B_NUM, 1024>>>(mask, qidx, pos, nv);
    rope_table<<<(S_LEN * 16) / 256, 256>>>(rt);
    // 2) fused QKV projection
    gemm_qkv<<<dim3(12, 64), 256>>>(x, W_in, qidx, pos, nv, rt,
                                    Vfull, Qc, Kc, Vc);
    // 3) split-K causal attention -> partial (O, l) per half
    flash_attn_c4<<<dim3(2 * NQB, H_NUM, B_NUM), 256, ATT_SMEM>>>(
        Qc, Kc, Vc, nv, op, lp);
    // 4) fused merge + masked v-copy -> attn
    merge_vcopy<<<dim3(S_LEN, B_NUM), 128>>>(op, lp, pos, mask, Vfull, attn);
    // 5) out = attn @ W_out^T
    gemm_tf32<128, 128, 32><<<dim3(4, 64), 256>>>(attn, W_out, out,
                                                  M_ROWS, E_DIM, E_DIM);
}

// round 16
// speedup vs baseline: 1.1741x; 1.1741x over previous
#include <cuda_runtime.h>
#include <cuda_fp16.h>
#include <float.h>

#define E_DIM 512
#define H_NUM 8
#define D_DIM 64
#define S_LEN 2048
#define B_NUM 4
#define M_ROWS (B_NUM * S_LEN)   // 8192
#define NQB (S_LEN / 128)        // 16 q-tiles per (b,h)

// Scratch (no allocations allowed). Device globals are zero-initialized; the
// compacted-tile tails [nv, pad128) are never written and stay zero.
__device__ float g_vfull[(size_t)M_ROWS * E_DIM];     // v projection (all rows)
__device__ float g_attn[(size_t)M_ROWS * E_DIM];      // attention output
__device__ float g_qc[(size_t)M_ROWS * E_DIM];        // compacted q (roped, scaled, tf32)
__device__ float g_kc[(size_t)M_ROWS * E_DIM];        // compacted k (roped, tf32)
__device__ float g_vc[(size_t)M_ROWS * E_DIM];        // compacted v (tf32)
__device__ int   g_qidx[M_ROWS];                      // compact pos -> orig s
__device__ int   g_pos[M_ROWS];                       // orig s -> compact pos | -1
__device__ int   g_nv[B_NUM];                         // valid count per batch
__device__ float g_rt[S_LEN * 32];                    // rope table: (cos,sin) x16
__device__ float g_opart[(size_t)2 * B_NUM * H_NUM * S_LEN * D_DIM];  // 67 MB
__device__ float g_lpart[(size_t)2 * B_NUM * H_NUM * S_LEN];          // 0.5 MB

// ---------------- helpers ----------------
__device__ __forceinline__ float to_tf32(float x) {
    float y; asm("cvt.rna.tf32.f32 %0, %1;" : "=f"(y) : "f"(x)); return y;
}
__device__ __forceinline__ unsigned f2h2(float lo, float hi) {
    unsigned r; asm("cvt.rn.f16x2.f32 %0, %1, %2;" : "=r"(r) : "f"(hi), "f"(lo));
    return r;
}
// tf32 k8 MMA (attention — unchanged, validated)
__device__ __forceinline__ void mma16n8k8(float c[4], const unsigned a[4],
                                          unsigned b0, unsigned b1) {
    asm volatile(
        "mma.sync.aligned.m16n8k8.row.col.f32.tf32.tf32.f32 "
        "{%0,%1,%2,%3}, {%4,%5,%6,%7}, {%8,%9}, {%0,%1,%2,%3};"
        : "+f"(c[0]), "+f"(c[1]), "+f"(c[2]), "+f"(c[3])
        : "r"(a[0]), "r"(a[1]), "r"(a[2]), "r"(a[3]), "r"(b0), "r"(b1));
}
// fp16 k16 MMA (GEMMs): same operand count, K=16 per step, fp32 accum.
__device__ __forceinline__ void mma16n8k16f16(float c[4], const unsigned a[4],
                                              unsigned b0, unsigned b1) {
    asm volatile(
        "mma.sync.aligned.m16n8k16.row.col.f32.f16.f16.f32 "
        "{%0,%1,%2,%3}, {%4,%5,%6,%7}, {%8,%9}, {%0,%1,%2,%3};"
        : "+f"(c[0]), "+f"(c[1]), "+f"(c[2]), "+f"(c[3])
        : "r"(a[0]), "r"(a[1]), "r"(a[2]), "r"(a[3]), "r"(b0), "r"(b1));
}
__device__ __forceinline__ unsigned smem_u32(const void* p) {
    return (unsigned)__cvta_generic_to_shared(p);
}
__device__ __forceinline__ void cp_async16(unsigned s, const void* g) {
    asm volatile("cp.async.cg.shared.global [%0], [%1], 16;" :: "r"(s), "l"(g));
}
__device__ __forceinline__ void cp_commit() {
    asm volatile("cp.async.commit_group;" ::: "memory");
}
template<int N>
__device__ __forceinline__ void cp_wait() {
    asm volatile("cp.async.wait_group %0;" :: "n"(N) : "memory");
}

// Q pre-scale folds log2(e): softmax numerators via exp2f.
#define Q_SCALE 0.18033688f   // 0.125 * 1.4426950408889634

// ---------------------------------------------------------------------------
// fp16 GEMM compute core, 4x2 warp tiling (warp = 32 rows x 64 cols).
// Tiles stored as uints (half2 pairs): row = 16 uints (32 halves) + 4 pad.
// Fragment uints land exactly on the m16n8k16 half-pair layout:
//   a0 = A[row g][k 16kt+2tig..+1]  = uint [ar+g][kt*8+tig]
//   a2 = A[row g][k 16kt+8+2tig..] = uint [ar+g][kt*8+tig+4]
//   b0 = B[n][k 16kt+2tig..+1]      = uint [br]  [kt*8+tig]   (B row-major n,k)
// Bank = (20*g + tig) % 32 is distinct across the warp: conflict-free.
// ---------------------------------------------------------------------------
#define GEMM_CHUNK_F16(As, Bs, Cacc, wm, wn, g, tig)                          \
    do {                                                                      \
        _Pragma("unroll")                                                     \
        for (int kt = 0; kt < 2; kt++) {                                      \
            unsigned afr[2][4];                                               \
            _Pragma("unroll")                                                 \
            for (int mt = 0; mt < 2; mt++) {                                  \
                int ar = (wm) * 32 + mt * 16;                                 \
                afr[mt][0] = As[ar + (g)][kt * 8 + (tig)];                    \
                afr[mt][1] = As[ar + (g) + 8][kt * 8 + (tig)];                \
                afr[mt][2] = As[ar + (g)][kt * 8 + (tig) + 4];                \
                afr[mt][3] = As[ar + (g) + 8][kt * 8 + (tig) + 4];            \
            }                                                                 \
            _Pragma("unroll")                                                 \
            for (int nt = 0; nt < 8; nt++) {                                  \
                int br = (wn) * 64 + nt * 8 + (g);                            \
                unsigned b0 = Bs[br][kt * 8 + (tig)];                         \
                unsigned b1 = Bs[br][kt * 8 + (tig) + 4];                     \
                mma16n8k16f16(Cacc[0][nt], afr[0], b0, b1);                   \
                mma16n8k16f16(Cacc[1][nt], afr[1], b0, b1);                   \
            }                                                                 \
        }                                                                     \
    } while (0)

// store one staged float4 (4 k-values) as 2 packed half2 uints
#define STAGE_H2(Tile, r, c4, p)                                              \
    do {                                                                      \
        uint2 u;                                                              \
        u.x = f2h2((p).x, (p).y);                                             \
        u.y = f2h2((p).z, (p).w);                                             \
        *(uint2*)&Tile[r][(c4) >> 1] = u;                                     \
    } while (0)

// ---------------------------------------------------------------------------
// Fused QKV projection (grid (12, 64)), fp16 tensor cores:
//   blockIdx.x 0..3  -> V columns on DENSE rows (Vfull + scatter Vc).
//   blockIdx.x 4..11 -> Q/K columns on GATHERED valid rows; early-exit;
//       fused RoPE+scale+tf32 epilogue into Qc/Kc (C layout unchanged).
// ---------------------------------------------------------------------------
__global__ __launch_bounds__(256)
void gemm_qkv(const float* __restrict__ x, const float* __restrict__ W_in,
              const int* __restrict__ qidx, const int* __restrict__ pos,
              const int* __restrict__ nv, const float* __restrict__ rt,
              float* __restrict__ Vfull, float* __restrict__ Qc,
              float* __restrict__ Kc, float* __restrict__ Vc) {
    const int BK = 32, K = 512;                 // BK in halves (k-elements)
    const int row0 = blockIdx.y * 128;
    const int bb = row0 >> 11;
    const int nvb = nv[bb];
    const bool isV = (blockIdx.x < 4);
    const int colblk = isV ? blockIdx.x : (blockIdx.x - 4);
    if (!isV && (row0 & 2047) >= ((nvb + 127) & ~127)) return;

    __shared__ unsigned As[128][20];            // 16 uints data + 4 pad
    __shared__ unsigned Bs[128][20];
    __shared__ int rowidx[128];

    const int tid = threadIdx.x;
    const int w = tid >> 5, lane = tid & 31;
    const int g = lane >> 2, tig = lane & 3;
    const int wm = w & 3, wn = w >> 2;

    for (int r = tid; r < 128; r += 256) {
        int idx;
        if (isV) {
            idx = row0 + r;
        } else {
            int p = (row0 & 2047) + r;
            int pc = (p < nvb) ? p : (nvb - 1);
            idx = (bb << 11) + qidx[(bb << 11) + pc];
        }
        rowidx[r] = idx;
    }
    __syncthreads();

    int rr[4];
    #pragma unroll
    for (int j = 0; j < 4; j++) rr[j] = rowidx[(tid + j * 256) >> 3];

    const float* Bp = W_in + (size_t)(isV ? (1024 + colblk * 128)
                                          : (colblk * 128)) * K;

    float Cacc[2][8][4];
    #pragma unroll
    for (int mt = 0; mt < 2; mt++)
        #pragma unroll
        for (int nt = 0; nt < 8; nt++)
            #pragma unroll
            for (int j = 0; j < 4; j++) Cacc[mt][nt][j] = 0.f;

    float4 pA[4], pB[4];
    #pragma unroll
    for (int j = 0; j < 4; j++) {
        int i = tid + j * 256, r = i >> 3, c4 = (i & 7) * 4;
        pA[j] = *(const float4*)&x[(size_t)rr[j] * K + c4];
        pB[j] = *(const float4*)&Bp[(size_t)r * K + c4];
    }
    #pragma unroll
    for (int j = 0; j < 4; j++) {
        int i = tid + j * 256, r = i >> 3, c4 = (i & 7) * 4;
        STAGE_H2(As, r, c4, pA[j]);
        STAGE_H2(Bs, r, c4, pB[j]);
    }
    __syncthreads();

    const int NC = K / BK;     // 16
    for (int ch = 0; ch < NC; ch++) {
        const bool more = (ch + 1) < NC;
        if (more) {
            const int kn = (ch + 1) * BK;
            #pragma unroll
            for (int j = 0; j < 4; j++) {
                int i = tid + j * 256, r = i >> 3, c4 = (i & 7) * 4;
                pA[j] = *(const float4*)&x[(size_t)rr[j] * K + kn + c4];
                pB[j] = *(const float4*)&Bp[(size_t)r * K + kn + c4];
            }
        }
        GEMM_CHUNK_F16(As, Bs, Cacc, wm, wn, g, tig);
        if (more) {
            __syncthreads();
            #pragma unroll
            for (int j = 0; j < 4; j++) {
                int i = tid + j * 256, r = i >> 3, c4 = (i & 7) * 4;
                STAGE_H2(As, r, c4, pA[j]);
                STAGE_H2(Bs, r, c4, pB[j]);
            }
            __syncthreads();
        }
    }

    if (isV) {
        #pragma unroll
        for (int mt = 0; mt < 2; mt++) {
            const int s1 = row0 + wm * 32 + mt * 16 + g, s2 = s1 + 8;
            const int ps1 = pos[s1], ps2 = pos[s2];
            #pragma unroll
            for (int nt = 0; nt < 8; nt++) {
                const int col = colblk * 128 + wn * 64 + nt * 8 + 2 * tig;
                {
                    float2 o; o.x = Cacc[mt][nt][0]; o.y = Cacc[mt][nt][1];
                    *(float2*)&Vfull[(size_t)s1 * E_DIM + col] = o;
                    if (ps1 >= 0) {
                        float2 t; t.x = to_tf32(o.x); t.y = to_tf32(o.y);
                        *(float2*)&Vc[(size_t)((bb << 11) + ps1) * E_DIM + col] = t;
                    }
                }
                {
                    float2 o; o.x = Cacc[mt][nt][2]; o.y = Cacc[mt][nt][3];
                    *(float2*)&Vfull[(size_t)s2 * E_DIM + col] = o;
                    if (ps2 >= 0) {
                        float2 t; t.x = to_tf32(o.x); t.y = to_tf32(o.y);
                        *(float2*)&Vc[(size_t)((bb << 11) + ps2) * E_DIM + col] = t;
                    }
                }
            }
        }
    } else {
        const int base = bb << 11;
        const int col0 = colblk * 128;
        const bool isQ = (col0 < 512);
        float* dst = isQ ? Qc : Kc;
        const float scale = isQ ? Q_SCALE : 1.0f;
        #pragma unroll
        for (int mt = 0; mt < 2; mt++) {
            const int pl1 = (row0 & 2047) + wm * 32 + mt * 16 + g;
            const int pl2 = pl1 + 8;
            const bool ok1 = pl1 < nvb, ok2 = pl2 < nvb;
            const int s1 = ok1 ? qidx[base + pl1] : 0;
            const int s2 = ok2 ? qidx[base + pl2] : 0;
            #pragma unroll
            for (int nt = 0; nt < 8; nt++) {
                const int col = col0 + wn * 64 + nt * 8 + 2 * tig;
                const int d = col & 63;
                const int cq = col & 511;
                if (ok1) {
                    float c0 = Cacc[mt][nt][0], c1 = Cacc[mt][nt][1];
                    if (d < 32) {
                        float2 t = *(const float2*)(rt + s1 * 32 + d);
                        float r0 = c0 * t.x - c1 * t.y;
                        float r1 = c0 * t.y + c1 * t.x;
                        c0 = r0; c1 = r1;
                    }
                    float2 o; o.x = to_tf32(c0 * scale); o.y = to_tf32(c1 * scale);
                    *(float2*)&dst[(size_t)(base + pl1) * E_DIM + cq] = o;
                }
                if (ok2) {
                    float c0 = Cacc[mt][nt][2], c1 = Cacc[mt][nt][3];
                    if (d < 32) {
                        float2 t = *(const float2*)(rt + s2 * 32 + d);
                        float r0 = c0 * t.x - c1 * t.y;
                        float r1 = c0 * t.y + c1 * t.x;
                        c0 = r0; c1 = r1;
                    }
                    float2 o; o.x = to_tf32(c0 * scale); o.y = to_tf32(c1 * scale);
                    *(float2*)&dst[(size_t)(base + pl2) * E_DIM + cq] = o;
                }
            }
        }
    }
}

// ---------------------------------------------------------------------------
// fp16 GEMM C = A @ B^T — output projection (4x2 warp tiling).
// ---------------------------------------------------------------------------
__global__ __launch_bounds__(256)
void gemm_f16(const float* __restrict__ A, const float* __restrict__ B,
              float* __restrict__ C, int M, int N, int K) {
    __shared__ unsigned As[128][20];
    __shared__ unsigned Bs[128][20];
    const int tid = threadIdx.x;
    const int w = tid >> 5, lane = tid & 31;
    const int g = lane >> 2, tig = lane & 3;
    const int wm = w & 3, wn = w >> 2;
    const int row0 = blockIdx.y * 128, col0 = blockIdx.x * 128;
    const int BK = 32;

    float Cacc[2][8][4];
    #pragma unroll
    for (int mt = 0; mt < 2; mt++)
        #pragma unroll
        for (int nt = 0; nt < 8; nt++)
            #pragma unroll
            for (int j = 0; j < 4; j++) Cacc[mt][nt][j] = 0.f;

    float4 pA[4], pB[4];
    #pragma unroll
    for (int j = 0; j < 4; j++) {
        int i = tid + j * 256, r = i >> 3, c4 = (i & 7) * 4;
        pA[j] = *(const float4*)&A[(size_t)(row0 + r) * K + c4];
        pB[j] = *(const float4*)&B[(size_t)(col0 + r) * K + c4];
    }
    #pragma unroll
    for (int j = 0; j < 4; j++) {
        int i = tid + j * 256, r = i >> 3, c4 = (i & 7) * 4;
        STAGE_H2(As, r, c4, pA[j]);
        STAGE_H2(Bs, r, c4, pB[j]);
    }
    __syncthreads();

    const int NC = K / BK;
    for (int ch = 0; ch < NC; ch++) {
        const bool more = (ch + 1) < NC;
        if (more) {
            const int kn = (ch + 1) * BK;
            #pragma unroll
            for (int j = 0; j < 4; j++) {
                int i = tid + j * 256, r = i >> 3, c4 = (i & 7) * 4;
                pA[j] = *(const float4*)&A[(size_t)(row0 + r) * K + kn + c4];
                pB[j] = *(const float4*)&B[(size_t)(col0 + r) * K + kn + c4];
            }
        }
        GEMM_CHUNK_F16(As, Bs, Cacc, wm, wn, g, tig);
        if (more) {
            __syncthreads();
            #pragma unroll
            for (int j = 0; j < 4; j++) {
                int i = tid + j * 256, r = i >> 3, c4 = (i & 7) * 4;
                STAGE_H2(As, r, c4, pA[j]);
                STAGE_H2(Bs, r, c4, pB[j]);
            }
            __syncthreads();
        }
    }

    #pragma unroll
    for (int mt = 0; mt < 2; mt++) {
        int r1 = row0 + wm * 32 + mt * 16 + g;
        #pragma unroll
        for (int nt = 0; nt < 8; nt++) {
            int col = col0 + wn * 64 + nt * 8 + 2 * tig;
            float2 o1; o1.x = Cacc[mt][nt][0]; o1.y = Cacc[mt][nt][1];
            float2 o2; o2.x = Cacc[mt][nt][2]; o2.y = Cacc[mt][nt][3];
            *(float2*)&C[(size_t)r1 * N + col] = o1;
            *(float2*)&C[(size_t)(r1 + 8) * N + col] = o2;
        }
    }
}

// ---------------------------------------------------------------------------
// Per-batch mask prefix scan; emits qidx, pos, nv.
// ---------------------------------------------------------------------------
__global__ void mask_compact(const int* __restrict__ mask,
                             int* __restrict__ qidx, int* __restrict__ pos,
                             int* __restrict__ nv) {
    __shared__ int ps[1024];
    const int b = blockIdx.x, t = threadIdx.x;
    const int m0 = mask[b * S_LEN + 2 * t] != 0;
    const int m1 = mask[b * S_LEN + 2 * t + 1] != 0;
    ps[t] = m0 + m1;
    __syncthreads();
    #pragma unroll
    for (int off = 1; off < 1024; off <<= 1) {
        int v = ps[t];
        int a = (t >= off) ? ps[t - off] : 0;
        __syncthreads();
        ps[t] = v + a;
        __syncthreads();
    }
    int excl = t ? ps[t - 1] : 0;
    int c0 = excl + m0;
    int c1 = c0 + m1;
    if (m0) qidx[b * S_LEN + c0 - 1] = 2 * t;
    if (m1) qidx[b * S_LEN + c1 - 1] = 2 * t + 1;
    pos[b * S_LEN + 2 * t]     = m0 ? (c0 - 1) : -1;
    pos[b * S_LEN + 2 * t + 1] = m1 ? (c1 - 1) : -1;
    if (t == 1023) nv[b] = c1;
}

// ---------------------------------------------------------------------------
// RoPE table.
// ---------------------------------------------------------------------------
__global__ void rope_table(float* __restrict__ rt) {
    int idx = blockIdx.x * blockDim.x + threadIdx.x;    // < 2048*16
    int pair = idx & 15, s = idx >> 4;
    float freq = powf(10000.f, -(float)(2 * pair) / 32.f);
    float sn, cs;
    sincosf((float)s * freq, &sn, &cs);
    rt[s * 32 + 2 * pair]     = cs;
    rt[s * 32 + 2 * pair + 1] = sn;
}

// ---------------------------------------------------------------------------
// Split-K tensor-core flash attention (tf32, single barrier per iteration —
// unchanged from R15, validated).
// ---------------------------------------------------------------------------
__global__ __launch_bounds__(256)
void flash_attn_c4(const float* __restrict__ Qc, const float* __restrict__ Kc,
                   const float* __restrict__ Vc, const int* __restrict__ nv,
                   float* __restrict__ opart, float* __restrict__ lpart) {
    extern __shared__ float sm[];
    float (*Ps)[68] = (float(*)[68])(sm + 17408);

    const int b = blockIdx.z, h = blockIdx.y;
    const int raw = gridDim.x - 1 - blockIdx.x;     // heavy blocks first
    const int qb = raw >> 1, half = raw & 1;
    const int n = nv[b];
    if (qb * 128 >= n) return;

    const int itStart = half ? (qb + 1) : 0;
    const int itEnd   = half ? (2 * qb + 2) : (qb + 1);   // exclusive

    const int tid = threadIdx.x;
    const int w = tid >> 5, lane = tid & 31;
    const int g = lane >> 2, tig = lane & 3;
    const int p1 = qb * 128 + w * 16 + g, p2 = p1 + 8;

    const float* qsec = Qc + (size_t)(b * S_LEN) * E_DIM + h * D_DIM;
    const float* ksec = Kc + (size_t)(b * S_LEN) * E_DIM + h * D_DIM;
    const float* vsec = Vc + (size_t)(b * S_LEN) * E_DIM + h * D_DIM;

    {
        float* Kb = sm + (itStart & 1) * 8704;
        float* Vb = Kb + 64 * 68;
        const int t00 = itStart * 64;
        #pragma unroll
        for (int j = 0; j < 4; j++) {
            int i = tid + j * 256;
            int r = i >> 4, c4 = (i & 15) * 4;
            cp_async16(smem_u32(&Kb[r * 68 + c4]), ksec + (size_t)(t00 + r) * E_DIM + c4);
            cp_async16(smem_u32(&Vb[r * 68 + c4]), vsec + (size_t)(t00 + r) * E_DIM + c4);
        }
        cp_commit();
    }

    for (int i = tid; i < 128 * 16; i += 256) {
        int r = i >> 4, c4 = (i & 15) * 4;
        *(float4*)&Ps[r][c4] =
            *(const float4*)(qsec + (size_t)(qb * 128 + r) * E_DIM + c4);
    }
    __syncthreads();
    unsigned qa[8][4];
    #pragma unroll
    for (int kt = 0; kt < 8; kt++) {
        qa[kt][0] = __float_as_uint(Ps[w * 16 + g][kt * 8 + tig]);
        qa[kt][1] = __float_as_uint(Ps[w * 16 + g + 8][kt * 8 + tig]);
        qa[kt][2] = __float_as_uint(Ps[w * 16 + g][kt * 8 + tig + 4]);
        qa[kt][3] = __float_as_uint(Ps[w * 16 + g + 8][kt * 8 + tig + 4]);
    }

    float O[8][4];
    #pragma unroll
    for (int nt = 0; nt < 8; nt++)
        #pragma unroll
        for (int j = 0; j < 4; j++) O[nt][j] = 0.f;
    float l1 = 0.f, l2 = 0.f;

    for (int it = itStart; it < itEnd; ++it) {
        cp_wait<0>();
        __syncthreads();
        if (it + 1 < itEnd) {
            float* Kb = sm + ((it + 1) & 1) * 8704;
            float* Vb = Kb + 64 * 68;
            const int t0n = (it + 1) * 64;
            #pragma unroll
            for (int j = 0; j < 4; j++) {
                int i = tid + j * 256;
                int r = i >> 4, c4 = (i & 15) * 4;
                cp_async16(smem_u32(&Kb[r * 68 + c4]),
                           ksec + (size_t)(t0n + r) * E_DIM + c4);
                cp_async16(smem_u32(&Vb[r * 68 + c4]),
                           vsec + (size_t)(t0n + r) * E_DIM + c4);
            }
            cp_commit();
        }

        const float* Kb = sm + (it & 1) * 8704;
        const float* Vb = Kb + 64 * 68;
        const int t0 = it * 64;

        float C[8][4];
        #pragma unroll
        for (int nt = 0; nt < 8; nt++)
            #pragma unroll
            for (int j = 0; j < 4; j++) C[nt][j] = 0.f;
        #pragma unroll
        for (int kt = 0; kt < 8; kt++) {
            #pragma unroll
            for (int nt = 0; nt < 8; nt++) {
                unsigned b0 = __float_as_uint(Kb[(nt * 8 + g) * 68 + kt * 8 + tig]);
                unsigned b1 = __float_as_uint(Kb[(nt * 8 + g) * 68 + kt * 8 + tig + 4]);
                mma16n8k8(C[nt], qa[kt], b0, b1);
            }
        }

        if (it >= 2 * qb) {
            #pragma unroll
            for (int nt = 0; nt < 8; nt++) {
                int tp = t0 + nt * 8 + 2 * tig;
                if (tp     > p1) C[nt][0] = -30000.f;
                if (tp + 1 > p1) C[nt][1] = -30000.f;
                if (tp     > p2) C[nt][2] = -30000.f;
                if (tp + 1 > p2) C[nt][3] = -30000.f;
            }
        }

        float sum1 = 0.f, sum2 = 0.f;
        #pragma unroll
        for (int nt = 0; nt < 8; nt++) {
            C[nt][0] = exp2f(C[nt][0]); sum1 += C[nt][0];
            C[nt][1] = exp2f(C[nt][1]); sum1 += C[nt][1];
            C[nt][2] = exp2f(C[nt][2]); sum2 += C[nt][2];
            C[nt][3] = exp2f(C[nt][3]); sum2 += C[nt][3];
        }
        sum1 += __shfl_xor_sync(0xffffffffu, sum1, 1);
        sum1 += __shfl_xor_sync(0xffffffffu, sum1, 2);
        sum2 += __shfl_xor_sync(0xffffffffu, sum2, 1);
        sum2 += __shfl_xor_sync(0xffffffffu, sum2, 2);
        l1 += sum1;
        l2 += sum2;

        #pragma unroll
        for (int nt = 0; nt < 8; nt++) {
            int r = w * 16 + g, c = nt * 8 + 2 * tig;
            Ps[r][c]         = to_tf32(C[nt][0]);
            Ps[r][c + 1]     = to_tf32(C[nt][1]);
            Ps[r + 8][c]     = to_tf32(C[nt][2]);
            Ps[r + 8][c + 1] = to_tf32(C[nt][3]);
        }
        __syncwarp();

        #pragma unroll
        for (int kt = 0; kt < 8; kt++) {
            unsigned pa[4];
            pa[0] = __float_as_uint(Ps[w * 16 + g][kt * 8 + tig]);
            pa[1] = __float_as_uint(Ps[w * 16 + g + 8][kt * 8 + tig]);
            pa[2] = __float_as_uint(Ps[w * 16 + g][kt * 8 + tig + 4]);
            pa[3] = __float_as_uint(Ps[w * 16 + g + 8][kt * 8 + tig + 4]);
            #pragma unroll
            for (int nt = 0; nt < 8; nt++) {
                unsigned b0 = __float_as_uint(Vb[(kt * 8 + tig) * 68 + nt * 8 + g]);
                unsigned b1 = __float_as_uint(Vb[(kt * 8 + tig + 4) * 68 + nt * 8 + g]);
                mma16n8k8(O[nt], pa, b0, b1);
            }
        }
    }

    const size_t base = ((((size_t)half * B_NUM + b) * H_NUM + h) * S_LEN);
    const int ok1 = (p1 < n), ok2 = (p2 < n);
    float* op1 = opart + (base + p1) * D_DIM;
    float* op2 = opart + (base + p2) * D_DIM;
    #pragma unroll
    for (int nt = 0; nt < 8; nt++) {
        int c = nt * 8 + 2 * tig;
        if (ok1) { float2 o; o.x = O[nt][0]; o.y = O[nt][1]; *(float2*)(op1 + c) = o; }
        if (ok2) { float2 o; o.x = O[nt][2]; o.y = O[nt][3]; *(float2*)(op2 + c) = o; }
    }
    if (tig == 0) {
        if (ok1) lpart[base + p1] = l1;
        if (ok2) lpart[base + p2] = l2;
    }
}

// ---------------------------------------------------------------------------
// Fused merge + masked v-copy.
// ---------------------------------------------------------------------------
__global__ void merge_vcopy(const float* __restrict__ opart,
                            const float* __restrict__ lpart,
                            const int* __restrict__ pos,
                            const int* __restrict__ mask,
                            const float* __restrict__ Vfull,
                            float* __restrict__ out) {
    const int b = blockIdx.y, s = blockIdx.x, t = threadIdx.x;
    if (mask[b * S_LEN + s] == 0) {
        const float4* src = (const float4*)(Vfull + (size_t)(b * S_LEN + s) * E_DIM);
        ((float4*)(out + (size_t)(b * S_LEN + s) * E_DIM))[t] = src[t];
        return;
    }
    const int p = pos[b * S_LEN + s];
    const int h = t >> 4, c4 = (t & 15) * 4;
    const size_t r0 = ((((size_t)0 * B_NUM + b) * H_NUM + h) * S_LEN + p);
    const size_t r1 = ((((size_t)1 * B_NUM + b) * H_NUM + h) * S_LEN + p);
    const float inv = 1.f / (lpart[r0] + lpart[r1]);
    float4 o0 = *(const float4*)(opart + r0 * D_DIM + c4);
    float4 o1 = *(const float4*)(opart + r1 * D_DIM + c4);
    float4 o;
    o.x = (o0.x + o1.x) * inv; o.y = (o0.y + o1.y) * inv;
    o.z = (o0.z + o1.z) * inv; o.w = (o0.w + o1.w) * inv;
    *(float4*)(out + (size_t)(b * S_LEN + s) * E_DIM + h * D_DIM + c4) = o;
}

// ---------------------------------------------------------------------------
extern "C" void kernel_launch(void* const* d_in, const int* in_sizes, int n_in,
                              void* d_out, int out_size) {
    const float* x     = (const float*)d_in[0];
    const int*   mask  = (const int*)d_in[1];     // bool -> int32 in harness
    const float* W_in  = (const float*)d_in[2];
    const float* W_out = (const float*)d_in[3];
    float*       out   = (float*)d_out;

    float *Vfull, *attn, *Qc, *Kc, *Vc, *rt, *op, *lp; int *qidx, *pos, *nv;
    cudaGetSymbolAddress((void**)&Vfull, g_vfull);
    cudaGetSymbolAddress((void**)&attn,  g_attn);
    cudaGetSymbolAddress((void**)&Qc,    g_qc);
    cudaGetSymbolAddress((void**)&Kc,    g_kc);
    cudaGetSymbolAddress((void**)&Vc,    g_vc);
    cudaGetSymbolAddress((void**)&rt,    g_rt);
    cudaGetSymbolAddress((void**)&op,    g_opart);
    cudaGetSymbolAddress((void**)&lp,    g_lpart);
    cudaGetSymbolAddress((void**)&qidx,  g_qidx);
    cudaGetSymbolAddress((void**)&pos,   g_pos);
    cudaGetSymbolAddress((void**)&nv,    g_nv);

    const int ATT_SMEM = 26112 * sizeof(float);   // 104448 B
    cudaFuncSetAttribute(flash_attn_c4,
                         cudaFuncAttributeMaxDynamicSharedMemorySize, ATT_SMEM);

    // 1) mask scan + rope table
    mask_compact<<<B_NUM, 1024>>>(mask, qidx, pos, nv);
    rope_table<<<(S_LEN * 16) / 256, 256>>>(rt);
    // 2) fused QKV projection (fp16 tensor cores, fp32 accumulate)
    gemm_qkv<<<dim3(12, 64), 256>>>(x, W_in, qidx, pos, nv, rt,
                                    Vfull, Qc, Kc, Vc);
    // 3) split-K causal attention -> partial (O, l) per half
    flash_attn_c4<<<dim3(2 * NQB, H_NUM, B_NUM), 256, ATT_SMEM>>>(
        Qc, Kc, Vc, nv, op, lp);
    // 4) fused merge + masked v-copy -> attn
    merge_vcopy<<<dim3(S_LEN, B_NUM), 128>>>(op, lp, pos, mask, Vfull, attn);
    // 5) out = attn @ W_out^T  (fp16 tensor cores)
    gemm_f16<<<dim3(4, 64), 256>>>(attn, W_out, out, M_ROWS, E_DIM, E_DIM);
}

// round 17
// speedup vs baseline: 1.5098x; 1.2859x over previous
#include <cuda_runtime.h>
#include <cuda_fp16.h>
#include <float.h>

#define E_DIM 512
#define H_NUM 8
#define D_DIM 64
#define S_LEN 2048
#define B_NUM 4
#define M_ROWS (B_NUM * S_LEN)   // 8192
#define NQB (S_LEN / 128)        // 16 q-tiles per (b,h)

// Scratch (no allocations allowed). Device globals are zero-initialized; the
// compacted tails [nv, pad128) are never written and stay zero.
__device__ float  g_vfull[(size_t)M_ROWS * E_DIM];    // v projection (fp32, all rows)
__device__ float  g_attn[(size_t)M_ROWS * E_DIM];     // attention output
__device__ __half g_qc[(size_t)M_ROWS * E_DIM];       // compacted q (roped, scaled, fp16)
__device__ __half g_kc[(size_t)M_ROWS * E_DIM];       // compacted k (roped, fp16)
__device__ __half g_vt[(size_t)B_NUM * H_NUM * D_DIM * S_LEN]; // V transposed fp16
__device__ int    g_qidx[M_ROWS];                     // compact pos -> orig s
__device__ int    g_pos[M_ROWS];                      // orig s -> compact pos | -1
__device__ int    g_nv[B_NUM];                        // valid count per batch
__device__ float  g_rt[S_LEN * 32];                   // rope table: (cos,sin) x16
__device__ float  g_opart[(size_t)2 * B_NUM * H_NUM * S_LEN * D_DIM];  // 67 MB
__device__ float  g_lpart[(size_t)2 * B_NUM * H_NUM * S_LEN];          // 0.5 MB

// ---------------- helpers ----------------
__device__ __forceinline__ unsigned f2h2(float lo, float hi) {
    unsigned r; asm("cvt.rn.f16x2.f32 %0, %1, %2;" : "=r"(r) : "f"(hi), "f"(lo));
    return r;
}
// fp16 k16 MMA, fp32 accumulate (used everywhere now)
__device__ __forceinline__ void mma16n8k16f16(float c[4], const unsigned a[4],
                                              unsigned b0, unsigned b1) {
    asm volatile(
        "mma.sync.aligned.m16n8k16.row.col.f32.f16.f16.f32 "
        "{%0,%1,%2,%3}, {%4,%5,%6,%7}, {%8,%9}, {%0,%1,%2,%3};"
        : "+f"(c[0]), "+f"(c[1]), "+f"(c[2]), "+f"(c[3])
        : "r"(a[0]), "r"(a[1]), "r"(a[2]), "r"(a[3]), "r"(b0), "r"(b1));
}
__device__ __forceinline__ unsigned smem_u32(const void* p) {
    return (unsigned)__cvta_generic_to_shared(p);
}
__device__ __forceinline__ void cp_async8(unsigned s, const void* g) {
    asm volatile("cp.async.ca.shared.global [%0], [%1], 8;" :: "r"(s), "l"(g));
}
__device__ __forceinline__ void cp_commit() {
    asm volatile("cp.async.commit_group;" ::: "memory");
}
template<int N>
__device__ __forceinline__ void cp_wait() {
    asm volatile("cp.async.wait_group %0;" :: "n"(N) : "memory");
}

// Q pre-scale folds log2(e): softmax numerators via exp2f.
#define Q_SCALE 0.18033688f   // 0.125 * 1.4426950408889634

// ---------------------------------------------------------------------------
// fp16 GEMM compute core, 4x2 warp tiling (unchanged from R16, validated).
// Tiles: uints (half2 pairs), row = 16 uints + 4 pad (bank = 4r+c distinct).
// ---------------------------------------------------------------------------
#define GEMM_CHUNK_F16(As, Bs, Cacc, wm, wn, g, tig)                          \
    do {                                                                      \
        _Pragma("unroll")                                                     \
        for (int kt = 0; kt < 2; kt++) {                                      \
            unsigned afr[2][4];                                               \
            _Pragma("unroll")                                                 \
            for (int mt = 0; mt < 2; mt++) {                                  \
                int ar = (wm) * 32 + mt * 16;                                 \
                afr[mt][0] = As[ar + (g)][kt * 8 + (tig)];                    \
                afr[mt][1] = As[ar + (g) + 8][kt * 8 + (tig)];                \
                afr[mt][2] = As[ar + (g)][kt * 8 + (tig) + 4];                \
                afr[mt][3] = As[ar + (g) + 8][kt * 8 + (tig) + 4];            \
            }                                                                 \
            _Pragma("unroll")                                                 \
            for (int nt = 0; nt < 8; nt++) {                                  \
                int br = (wn) * 64 + nt * 8 + (g);                            \
                unsigned b0 = Bs[br][kt * 8 + (tig)];                         \
                unsigned b1 = Bs[br][kt * 8 + (tig) + 4];                     \
                mma16n8k16f16(Cacc[0][nt], afr[0], b0, b1);                   \
                mma16n8k16f16(Cacc[1][nt], afr[1], b0, b1);                   \
            }                                                                 \
        }                                                                     \
    } while (0)

#define STAGE_H2(Tile, r, c4, p)                                              \
    do {                                                                      \
        uint2 u;                                                              \
        u.x = f2h2((p).x, (p).y);                                             \
        u.y = f2h2((p).z, (p).w);                                             \
        *(uint2*)&Tile[r][(c4) >> 1] = u;                                     \
    } while (0)

// ---------------------------------------------------------------------------
// Fused QKV projection (grid (12, 64)), fp16 tensor cores:
//   blockIdx.x 0..3  -> V columns on DENSE rows: Vfull (fp32) + TRANSPOSED
//       fp16 scatter into Vt[(b*H+h)*64+d][pos].
//   blockIdx.x 4..11 -> Q/K columns on GATHERED valid rows; early-exit;
//       fused RoPE+scale epilogue, fp16 half2 into Qc/Kc.
// ---------------------------------------------------------------------------
__global__ __launch_bounds__(256)
void gemm_qkv(const float* __restrict__ x, const float* __restrict__ W_in,
              const int* __restrict__ qidx, const int* __restrict__ pos,
              const int* __restrict__ nv, const float* __restrict__ rt,
              float* __restrict__ Vfull, __half* __restrict__ Qc,
              __half* __restrict__ Kc, __half* __restrict__ Vt) {
    const int BK = 32, K = 512;
    const int row0 = blockIdx.y * 128;
    const int bb = row0 >> 11;
    const int nvb = nv[bb];
    const bool isV = (blockIdx.x < 4);
    const int colblk = isV ? blockIdx.x : (blockIdx.x - 4);
    if (!isV && (row0 & 2047) >= ((nvb + 127) & ~127)) return;

    __shared__ unsigned As[128][20];
    __shared__ unsigned Bs[128][20];
    __shared__ int rowidx[128];

    const int tid = threadIdx.x;
    const int w = tid >> 5, lane = tid & 31;
    const int g = lane >> 2, tig = lane & 3;
    const int wm = w & 3, wn = w >> 2;

    for (int r = tid; r < 128; r += 256) {
        int idx;
        if (isV) {
            idx = row0 + r;
        } else {
            int p = (row0 & 2047) + r;
            int pc = (p < nvb) ? p : (nvb - 1);
            idx = (bb << 11) + qidx[(bb << 11) + pc];
        }
        rowidx[r] = idx;
    }
    __syncthreads();

    int rr[4];
    #pragma unroll
    for (int j = 0; j < 4; j++) rr[j] = rowidx[(tid + j * 256) >> 3];

    const float* Bp = W_in + (size_t)(isV ? (1024 + colblk * 128)
                                          : (colblk * 128)) * K;

    float Cacc[2][8][4];
    #pragma unroll
    for (int mt = 0; mt < 2; mt++)
        #pragma unroll
        for (int nt = 0; nt < 8; nt++)
            #pragma unroll
            for (int j = 0; j < 4; j++) Cacc[mt][nt][j] = 0.f;

    float4 pA[4], pB[4];
    #pragma unroll
    for (int j = 0; j < 4; j++) {
        int i = tid + j * 256, r = i >> 3, c4 = (i & 7) * 4;
        pA[j] = *(const float4*)&x[(size_t)rr[j] * K + c4];
        pB[j] = *(const float4*)&Bp[(size_t)r * K + c4];
    }
    #pragma unroll
    for (int j = 0; j < 4; j++) {
        int i = tid + j * 256, r = i >> 3, c4 = (i & 7) * 4;
        STAGE_H2(As, r, c4, pA[j]);
        STAGE_H2(Bs, r, c4, pB[j]);
    }
    __syncthreads();

    const int NC = K / BK;     // 16
    for (int ch = 0; ch < NC; ch++) {
        const bool more = (ch + 1) < NC;
        if (more) {
            const int kn = (ch + 1) * BK;
            #pragma unroll
            for (int j = 0; j < 4; j++) {
                int i = tid + j * 256, r = i >> 3, c4 = (i & 7) * 4;
                pA[j] = *(const float4*)&x[(size_t)rr[j] * K + kn + c4];
                pB[j] = *(const float4*)&Bp[(size_t)r * K + kn + c4];
            }
        }
        GEMM_CHUNK_F16(As, Bs, Cacc, wm, wn, g, tig);
        if (more) {
            __syncthreads();
            #pragma unroll
            for (int j = 0; j < 4; j++) {
                int i = tid + j * 256, r = i >> 3, c4 = (i & 7) * 4;
                STAGE_H2(As, r, c4, pA[j]);
                STAGE_H2(Bs, r, c4, pB[j]);
            }
            __syncthreads();
        }
    }

    if (isV) {
        #pragma unroll
        for (int mt = 0; mt < 2; mt++) {
            const int s1 = row0 + wm * 32 + mt * 16 + g, s2 = s1 + 8;
            const int ps1 = pos[s1], ps2 = pos[s2];
            #pragma unroll
            for (int nt = 0; nt < 8; nt++) {
                const int col = colblk * 128 + wn * 64 + nt * 8 + 2 * tig;
                const int hh = col >> 6, d = col & 63;       // head, dim (even)
                const size_t vrow = ((size_t)(bb * H_NUM + hh) * D_DIM + d) * S_LEN;
                {
                    float2 o; o.x = Cacc[mt][nt][0]; o.y = Cacc[mt][nt][1];
                    *(float2*)&Vfull[(size_t)s1 * E_DIM + col] = o;
                    if (ps1 >= 0) {
                        Vt[vrow + ps1]         = __float2half(o.x);
                        Vt[vrow + S_LEN + ps1] = __float2half(o.y);
                    }
                }
                {
                    float2 o; o.x = Cacc[mt][nt][2]; o.y = Cacc[mt][nt][3];
                    *(float2*)&Vfull[(size_t)s2 * E_DIM + col] = o;
                    if (ps2 >= 0) {
                        Vt[vrow + ps2]         = __float2half(o.x);
                        Vt[vrow + S_LEN + ps2] = __float2half(o.y);
                    }
                }
            }
        }
    } else {
        const int base = bb << 11;
        const int col0 = colblk * 128;
        const bool isQ = (col0 < 512);
        unsigned* dst = (unsigned*)(isQ ? Qc : Kc);
        const float scale = isQ ? Q_SCALE : 1.0f;
        #pragma unroll
        for (int mt = 0; mt < 2; mt++) {
            const int pl1 = (row0 & 2047) + wm * 32 + mt * 16 + g;
            const int pl2 = pl1 + 8;
            const bool ok1 = pl1 < nvb, ok2 = pl2 < nvb;
            const int s1 = ok1 ? qidx[base + pl1] : 0;
            const int s2 = ok2 ? qidx[base + pl2] : 0;
            #pragma unroll
            for (int nt = 0; nt < 8; nt++) {
                const int col = col0 + wn * 64 + nt * 8 + 2 * tig;
                const int d = col & 63;
                const int cq = col & 511;          // even
                if (ok1) {
                    float c0 = Cacc[mt][nt][0], c1 = Cacc[mt][nt][1];
                    if (d < 32) {
                        float2 t = *(const float2*)(rt + s1 * 32 + d);
                        float r0 = c0 * t.x - c1 * t.y;
                        float r1 = c0 * t.y + c1 * t.x;
                        c0 = r0; c1 = r1;
                    }
                    dst[(size_t)(base + pl1) * 256 + (cq >> 1)] =
                        f2h2(c0 * scale, c1 * scale);
                }
                if (ok2) {
                    float c0 = Cacc[mt][nt][2], c1 = Cacc[mt][nt][3];
                    if (d < 32) {
                        float2 t = *(const float2*)(rt + s2 * 32 + d);
                        float r0 = c0 * t.x - c1 * t.y;
                        float r1 = c0 * t.y + c1 * t.x;
                        c0 = r0; c1 = r1;
                    }
                    dst[(size_t)(base + pl2) * 256 + (cq >> 1)] =
                        f2h2(c0 * scale, c1 * scale);
                }
            }
        }
    }
}

// ---------------------------------------------------------------------------
// fp16 GEMM C = A @ B^T — output projection (unchanged from R16).
// ---------------------------------------------------------------------------
__global__ __launch_bounds__(256)
void gemm_f16(const float* __restrict__ A, const float* __restrict__ B,
              float* __restrict__ C, int M, int N, int K) {
    __shared__ unsigned As[128][20];
    __shared__ unsigned Bs[128][20];
    const int tid = threadIdx.x;
    const int w = tid >> 5, lane = tid & 31;
    const int g = lane >> 2, tig = lane & 3;
    const int wm = w & 3, wn = w >> 2;
    const int row0 = blockIdx.y * 128, col0 = blockIdx.x * 128;
    const int BK = 32;

    float Cacc[2][8][4];
    #pragma unroll
    for (int mt = 0; mt < 2; mt++)
        #pragma unroll
        for (int nt = 0; nt < 8; nt++)
            #pragma unroll
            for (int j = 0; j < 4; j++) Cacc[mt][nt][j] = 0.f;

    float4 pA[4], pB[4];
    #pragma unroll
    for (int j = 0; j < 4; j++) {
        int i = tid + j * 256, r = i >> 3, c4 = (i & 7) * 4;
        pA[j] = *(const float4*)&A[(size_t)(row0 + r) * K + c4];
        pB[j] = *(const float4*)&B[(size_t)(col0 + r) * K + c4];
    }
    #pragma unroll
    for (int j = 0; j < 4; j++) {
        int i = tid + j * 256, r = i >> 3, c4 = (i & 7) * 4;
        STAGE_H2(As, r, c4, pA[j]);
        STAGE_H2(Bs, r, c4, pB[j]);
    }
    __syncthreads();

    const int NC = K / BK;
    for (int ch = 0; ch < NC; ch++) {
        const bool more = (ch + 1) < NC;
        if (more) {
            const int kn = (ch + 1) * BK;
            #pragma unroll
            for (int j = 0; j < 4; j++) {
                int i = tid + j * 256, r = i >> 3, c4 = (i & 7) * 4;
                pA[j] = *(const float4*)&A[(size_t)(row0 + r) * K + kn + c4];
                pB[j] = *(const float4*)&B[(size_t)(col0 + r) * K + kn + c4];
            }
        }
        GEMM_CHUNK_F16(As, Bs, Cacc, wm, wn, g, tig);
        if (more) {
            __syncthreads();
            #pragma unroll
            for (int j = 0; j < 4; j++) {
                int i = tid + j * 256, r = i >> 3, c4 = (i & 7) * 4;
                STAGE_H2(As, r, c4, pA[j]);
                STAGE_H2(Bs, r, c4, pB[j]);
            }
            __syncthreads();
        }
    }

    #pragma unroll
    for (int mt = 0; mt < 2; mt++) {
        int r1 = row0 + wm * 32 + mt * 16 + g;
        #pragma unroll
        for (int nt = 0; nt < 8; nt++) {
            int col = col0 + wn * 64 + nt * 8 + 2 * tig;
            float2 o1; o1.x = Cacc[mt][nt][0]; o1.y = Cacc[mt][nt][1];
            float2 o2; o2.x = Cacc[mt][nt][2]; o2.y = Cacc[mt][nt][3];
            *(float2*)&C[(size_t)r1 * N + col] = o1;
            *(float2*)&C[(size_t)(r1 + 8) * N + col] = o2;
        }
    }
}

// ---------------------------------------------------------------------------
// Per-batch mask prefix scan; emits qidx, pos, nv.
// ---------------------------------------------------------------------------
__global__ void mask_compact(const int* __restrict__ mask,
                             int* __restrict__ qidx, int* __restrict__ pos,
                             int* __restrict__ nv) {
    __shared__ int ps[1024];
    const int b = blockIdx.x, t = threadIdx.x;
    const int m0 = mask[b * S_LEN + 2 * t] != 0;
    const int m1 = mask[b * S_LEN + 2 * t + 1] != 0;
    ps[t] = m0 + m1;
    __syncthreads();
    #pragma unroll
    for (int off = 1; off < 1024; off <<= 1) {
        int v = ps[t];
        int a = (t >= off) ? ps[t - off] : 0;
        __syncthreads();
        ps[t] = v + a;
        __syncthreads();
    }
    int excl = t ? ps[t - 1] : 0;
    int c0 = excl + m0;
    int c1 = c0 + m1;
    if (m0) qidx[b * S_LEN + c0 - 1] = 2 * t;
    if (m1) qidx[b * S_LEN + c1 - 1] = 2 * t + 1;
    pos[b * S_LEN + 2 * t]     = m0 ? (c0 - 1) : -1;
    pos[b * S_LEN + 2 * t + 1] = m1 ? (c1 - 1) : -1;
    if (t == 1023) nv[b] = c1;
}

// ---------------------------------------------------------------------------
// RoPE table.
// ---------------------------------------------------------------------------
__global__ void rope_table(float* __restrict__ rt) {
    int idx = blockIdx.x * blockDim.x + threadIdx.x;    // < 2048*16
    int pair = idx & 15, s = idx >> 4;
    float freq = powf(10000.f, -(float)(2 * pair) / 32.f);
    float sn, cs;
    sincosf((float)s * freq, &sn, &cs);
    rt[s * 32 + 2 * pair]     = cs;
    rt[s * 32 + 2 * pair + 1] = sn;
}

// ---------------------------------------------------------------------------
// Split-K fp16 flash attention. Smem (uints, stride 36 = 32 data + 4 pad):
//   buf b: K tile [64 keys][32] at b*4608, Vt tile [64 d][32 key-pairs] at +2304
//   Ps [128][32] at 9216 (Q staging, then P)
// Total 13824 uints = 55296 B. Bank = (4*row + col) % 32: fragment reads
// conflict-free. Fills via 8-byte cp.async (row stride 144 B, 8B aligned).
// QK: A=Q rows (k=d, 4 k16 steps); B=K tile rows.
// PV: A=P (k=key; thread's C[0],C[1] are adjacent keys -> single f2h2 uint);
//     B=Vt tile rows (d-major, key-pairs packed) — same pattern as GEMM B.
// fp32 accumulate; masking/softmax/l/merge identical to R15.
// ---------------------------------------------------------------------------
__global__ __launch_bounds__(256)
void flash_attn_f16(const unsigned* __restrict__ Qc,
                    const __half* __restrict__ Kc,
                    const __half* __restrict__ Vt,
                    const int* __restrict__ nv,
                    float* __restrict__ opart, float* __restrict__ lpart) {
    extern __shared__ unsigned smu[];
    unsigned* Ps = smu + 9216;

    const int b = blockIdx.z, h = blockIdx.y;
    const int raw = gridDim.x - 1 - blockIdx.x;     // heavy blocks first
    const int qb = raw >> 1, half = raw & 1;
    const int n = nv[b];
    if (qb * 128 >= n) return;

    const int itStart = half ? (qb + 1) : 0;
    const int itEnd   = half ? (2 * qb + 2) : (qb + 1);   // exclusive

    const int tid = threadIdx.x;
    const int w = tid >> 5, lane = tid & 31;
    const int g = lane >> 2, tig = lane & 3;
    const int p1 = qb * 128 + w * 16 + g, p2 = p1 + 8;

    const __half* ksec  = Kc + (size_t)(b * S_LEN) * E_DIM + h * D_DIM;
    const __half* vtsec = Vt + (size_t)(b * H_NUM + h) * D_DIM * S_LEN;

    // ---- fill helper: tile it -> buf (it&1). 8 chunks of 8B per thread ----
    #define ATT_FILL(T0, BUF)                                                 \
        do {                                                                  \
            unsigned* Kb = smu + (BUF) * 4608;                                \
            unsigned* Vb = Kb + 2304;                                         \
            _Pragma("unroll")                                                 \
            for (int j = 0; j < 4; j++) {                                     \
                int i = tid + j * 256;          /* 0..1023 */                 \
                int r = i >> 4, h0 = (i & 15) * 4;                            \
                cp_async8(smem_u32(&Kb[r * 36 + (i & 15) * 2]),               \
                          ksec + (size_t)((T0) + r) * E_DIM + h0);            \
                cp_async8(smem_u32(&Vb[r * 36 + (i & 15) * 2]),               \
                          vtsec + (size_t)r * S_LEN + (T0) + h0);             \
            }                                                                 \
            cp_commit();                                                      \
        } while (0)

    ATT_FILL(itStart * 64, itStart & 1);

    // ---- stage Q tile into Ps (uint2 = 4 halves) ----
    {
        const unsigned* qu = Qc + ((size_t)(b * S_LEN + qb * 128) * 256) + h * 32;
        for (int i = tid; i < 2048; i += 256) {
            int r = i >> 4, c2 = (i & 15) * 2;
            *(uint2*)&Ps[r * 36 + c2] = *(const uint2*)&qu[(size_t)r * 256 + c2];
        }
    }
    __syncthreads();
    unsigned qa[4][4];
    #pragma unroll
    for (int kt = 0; kt < 4; kt++) {
        qa[kt][0] = Ps[(w * 16 + g) * 36 + kt * 8 + tig];
        qa[kt][1] = Ps[(w * 16 + g + 8) * 36 + kt * 8 + tig];
        qa[kt][2] = Ps[(w * 16 + g) * 36 + kt * 8 + tig + 4];
        qa[kt][3] = Ps[(w * 16 + g + 8) * 36 + kt * 8 + tig + 4];
    }

    float O[8][4];
    #pragma unroll
    for (int nt = 0; nt < 8; nt++)
        #pragma unroll
        for (int j = 0; j < 4; j++) O[nt][j] = 0.f;
    float l1 = 0.f, l2 = 0.f;

    for (int it = itStart; it < itEnd; ++it) {
        cp_wait<0>();
        __syncthreads();        // publish tile it; all warps past compute(it-1)
        if (it + 1 < itEnd) ATT_FILL((it + 1) * 64, (it + 1) & 1);

        const unsigned* Kb = smu + (it & 1) * 4608;
        const unsigned* Vb = Kb + 2304;
        const int t0 = it * 64;

        // ---- S = Q @ K^T (fp16 k16) ----
        float C[8][4];
        #pragma unroll
        for (int nt = 0; nt < 8; nt++)
            #pragma unroll
            for (int j = 0; j < 4; j++) C[nt][j] = 0.f;
        #pragma unroll
        for (int kt = 0; kt < 4; kt++) {
            #pragma unroll
            for (int nt = 0; nt < 8; nt++) {
                unsigned b0 = Kb[(nt * 8 + g) * 36 + kt * 8 + tig];
                unsigned b1 = Kb[(nt * 8 + g) * 36 + kt * 8 + tig + 4];
                mma16n8k16f16(C[nt], qa[kt], b0, b1);
            }
        }

        if (it >= 2 * qb) {
            #pragma unroll
            for (int nt = 0; nt < 8; nt++) {
                int tp = t0 + nt * 8 + 2 * tig;
                if (tp     > p1) C[nt][0] = -30000.f;
                if (tp + 1 > p1) C[nt][1] = -30000.f;
                if (tp     > p2) C[nt][2] = -30000.f;
                if (tp + 1 > p2) C[nt][3] = -30000.f;
            }
        }

        float sum1 = 0.f, sum2 = 0.f;
        #pragma unroll
        for (int nt = 0; nt < 8; nt++) {
            C[nt][0] = exp2f(C[nt][0]); sum1 += C[nt][0];
            C[nt][1] = exp2f(C[nt][1]); sum1 += C[nt][1];
            C[nt][2] = exp2f(C[nt][2]); sum2 += C[nt][2];
            C[nt][3] = exp2f(C[nt][3]); sum2 += C[nt][3];
        }
        sum1 += __shfl_xor_sync(0xffffffffu, sum1, 1);
        sum1 += __shfl_xor_sync(0xffffffffu, sum1, 2);
        sum2 += __shfl_xor_sync(0xffffffffu, sum2, 1);
        sum2 += __shfl_xor_sync(0xffffffffu, sum2, 2);
        l1 += sum1;
        l2 += sum2;

        // ---- P (fp16 half2 pairs) into Ps: warp-private rows ----
        #pragma unroll
        for (int nt = 0; nt < 8; nt++) {
            Ps[(w * 16 + g) * 36 + nt * 4 + tig]     = f2h2(C[nt][0], C[nt][1]);
            Ps[(w * 16 + g + 8) * 36 + nt * 4 + tig] = f2h2(C[nt][2], C[nt][3]);
        }
        __syncwarp();

        // ---- O += P @ V (fp16 k16, B from transposed Vt tile) ----
        #pragma unroll
        for (int kt = 0; kt < 4; kt++) {
            unsigned pa[4];
            pa[0] = Ps[(w * 16 + g) * 36 + kt * 8 + tig];
            pa[1] = Ps[(w * 16 + g + 8) * 36 + kt * 8 + tig];
            pa[2] = Ps[(w * 16 + g) * 36 + kt * 8 + tig + 4];
            pa[3] = Ps[(w * 16 + g + 8) * 36 + kt * 8 + tig + 4];
            #pragma unroll
            for (int nt = 0; nt < 8; nt++) {
                unsigned b0 = Vb[(nt * 8 + g) * 36 + kt * 8 + tig];
                unsigned b1 = Vb[(nt * 8 + g) * 36 + kt * 8 + tig + 4];
                mma16n8k16f16(O[nt], pa, b0, b1);
            }
        }
    }

    const size_t base = ((((size_t)half * B_NUM + b) * H_NUM + h) * S_LEN);
    const int ok1 = (p1 < n), ok2 = (p2 < n);
    float* op1 = opart + (base + p1) * D_DIM;
    float* op2 = opart + (base + p2) * D_DIM;
    #pragma unroll
    for (int nt = 0; nt < 8; nt++) {
        int c = nt * 8 + 2 * tig;
        if (ok1) { float2 o; o.x = O[nt][0]; o.y = O[nt][1]; *(float2*)(op1 + c) = o; }
        if (ok2) { float2 o; o.x = O[nt][2]; o.y = O[nt][3]; *(float2*)(op2 + c) = o; }
    }
    if (tig == 0) {
        if (ok1) lpart[base + p1] = l1;
        if (ok2) lpart[base + p2] = l2;
    }
    #undef ATT_FILL
}

// ---------------------------------------------------------------------------
// Fused merge + masked v-copy (unchanged).
// ---------------------------------------------------------------------------
__global__ void merge_vcopy(const float* __restrict__ opart,
                            const float* __restrict__ lpart,
                            const int* __restrict__ pos,
                            const int* __restrict__ mask,
                            const float* __restrict__ Vfull,
                            float* __restrict__ out) {
    const int b = blockIdx.y, s = blockIdx.x, t = threadIdx.x;
    if (mask[b * S_LEN + s] == 0) {
        const float4* src = (const float4*)(Vfull + (size_t)(b * S_LEN + s) * E_DIM);
        ((float4*)(out + (size_t)(b * S_LEN + s) * E_DIM))[t] = src[t];
        return;
    }
    const int p = pos[b * S_LEN + s];
    const int h = t >> 4, c4 = (t & 15) * 4;
    const size_t r0 = ((((size_t)0 * B_NUM + b) * H_NUM + h) * S_LEN + p);
    const size_t r1 = ((((size_t)1 * B_NUM + b) * H_NUM + h) * S_LEN + p);
    const float inv = 1.f / (lpart[r0] + lpart[r1]);
    float4 o0 = *(const float4*)(opart + r0 * D_DIM + c4);
    float4 o1 = *(const float4*)(opart + r1 * D_DIM + c4);
    float4 o;
    o.x = (o0.x + o1.x) * inv; o.y = (o0.y + o1.y) * inv;
    o.z = (o0.z + o1.z) * inv; o.w = (o0.w + o1.w) * inv;
    *(float4*)(out + (size_t)(b * S_LEN + s) * E_DIM + h * D_DIM + c4) = o;
}

// ---------------------------------------------------------------------------
extern "C" void kernel_launch(void* const* d_in, const int* in_sizes, int n_in,
                              void* d_out, int out_size) {
    const float* x     = (const float*)d_in[0];
    const int*   mask  = (const int*)d_in[1];     // bool -> int32 in harness
    const float* W_in  = (const float*)d_in[2];
    const float* W_out = (const float*)d_in[3];
    float*       out   = (float*)d_out;

    float *Vfull, *attn, *rt, *op, *lp; __half *Qc, *Kc, *Vt;
    int *qidx, *pos, *nv;
    cudaGetSymbolAddress((void**)&Vfull, g_vfull);
    cudaGetSymbolAddress((void**)&attn,  g_attn);
    cudaGetSymbolAddress((void**)&Qc,    g_qc);
    cudaGetSymbolAddress((void**)&Kc,    g_kc);
    cudaGetSymbolAddress((void**)&Vt,    g_vt);
    cudaGetSymbolAddress((void**)&rt,    g_rt);
    cudaGetSymbolAddress((void**)&op,    g_opart);
    cudaGetSymbolAddress((void**)&lp,    g_lpart);
    cudaGetSymbolAddress((void**)&qidx,  g_qidx);
    cudaGetSymbolAddress((void**)&pos,   g_pos);
    cudaGetSymbolAddress((void**)&nv,    g_nv);

    const int ATT_SMEM = 13824 * sizeof(unsigned);   // 55296 B
    cudaFuncSetAttribute(flash_attn_f16,
                         cudaFuncAttributeMaxDynamicSharedMemorySize, ATT_SMEM);

    // 1) mask scan + rope table
    mask_compact<<<B_NUM, 1024>>>(mask, qidx, pos, nv);
    rope_table<<<(S_LEN * 16) / 256, 256>>>(rt);
    // 2) fused QKV projection (fp16): Vfull fp32 + Vt fp16 transposed,
    //    Qc/Kc fp16 roped+scaled
    gemm_qkv<<<dim3(12, 64), 256>>>(x, W_in, qidx, pos, nv, rt,
                                    Vfull, Qc, Kc, Vt);
    // 3) split-K fp16 causal attention -> partial (O, l) per half
    flash_attn_f16<<<dim3(2 * NQB, H_NUM, B_NUM), 256, ATT_SMEM>>>(
        (const unsigned*)Qc, Kc, Vt, nv, op, lp);
    // 4) fused merge + masked v-copy -> attn
    merge_vcopy<<<dim3(S_LEN, B_NUM), 128>>>(op, lp, pos, mask, Vfull, attn);
    // 5) out = attn @ W_out^T  (fp16 tensor cores)
    gemm_f16<<<dim3(4, 64), 256>>>(attn, W_out, out, M_ROWS, E_DIM, E_DIM);
}